// round 1
// baseline (speedup 1.0000x reference)
#include <cuda_runtime.h>

#define BATCH 4
#define T 2048
#define C 1024
#define H 64
#define M_TOTAL (BATCH * T)   // 8192

// Scratch for projected q, k, v  (allocation-free rule: __device__ globals)
__device__ float g_q[BATCH * T * H];
__device__ float g_k[BATCH * T * H];
__device__ float g_v[BATCH * T * H];

// ---------------------------------------------------------------------------
// Projection: out[m][h] = sum_c x[m][c] * W[h][c]
// M=8192, N=H=64, K=1024.  BM=64, BN=64, BK=32.  256 threads, 4x4 microtile.
// blockIdx.y selects which of Wq/Wk/Wv.
// ---------------------------------------------------------------------------
__global__ __launch_bounds__(256) void proj_kernel(
    const float* __restrict__ x,
    const float* __restrict__ Wq,
    const float* __restrict__ Wk,
    const float* __restrict__ Wv)
{
    const float* W;
    float* out;
    if (blockIdx.y == 0)      { W = Wq; out = g_q; }
    else if (blockIdx.y == 1) { W = Wk; out = g_k; }
    else                      { W = Wv; out = g_v; }

    __shared__ float As[32][68];   // [k][m], pad 68 keeps float4 alignment
    __shared__ float Bs[32][68];   // [k][h]

    const int tid = threadIdx.x;
    const int tm  = tid >> 4;       // 0..15
    const int tn  = tid & 15;       // 0..15
    const int m0  = tm * 4;
    const int h0  = tn * 4;
    const int mblk = blockIdx.x * 64;

    float acc[4][4] = {};

    for (int k0 = 0; k0 < C; k0 += 32) {
        // Load x tile: 64 rows x 32 k = 512 float4, 2 per thread.
        #pragma unroll
        for (int i = 0; i < 2; i++) {
            int idx = i * 256 + tid;
            int row = idx >> 3;           // 0..63
            int kq  = idx & 7;            // 0..7
            float4 a = *(const float4*)(x + (size_t)(mblk + row) * C + k0 + kq * 4);
            As[kq * 4 + 0][row] = a.x;
            As[kq * 4 + 1][row] = a.y;
            As[kq * 4 + 2][row] = a.z;
            As[kq * 4 + 3][row] = a.w;
        }
        // Load W tile: 64 rows (h) x 32 k.
        #pragma unroll
        for (int i = 0; i < 2; i++) {
            int idx = i * 256 + tid;
            int row = idx >> 3;
            int kq  = idx & 7;
            float4 b = *(const float4*)(W + (size_t)row * C + k0 + kq * 4);
            Bs[kq * 4 + 0][row] = b.x;
            Bs[kq * 4 + 1][row] = b.y;
            Bs[kq * 4 + 2][row] = b.z;
            Bs[kq * 4 + 3][row] = b.w;
        }
        __syncthreads();

        #pragma unroll
        for (int kk = 0; kk < 32; kk++) {
            float4 a = *(const float4*)&As[kk][m0];
            float4 b = *(const float4*)&Bs[kk][h0];
            acc[0][0] += a.x * b.x; acc[0][1] += a.x * b.y; acc[0][2] += a.x * b.z; acc[0][3] += a.x * b.w;
            acc[1][0] += a.y * b.x; acc[1][1] += a.y * b.y; acc[1][2] += a.y * b.z; acc[1][3] += a.y * b.w;
            acc[2][0] += a.z * b.x; acc[2][1] += a.z * b.y; acc[2][2] += a.z * b.z; acc[2][3] += a.z * b.w;
            acc[3][0] += a.w * b.x; acc[3][1] += a.w * b.y; acc[3][2] += a.w * b.z; acc[3][3] += a.w * b.w;
        }
        __syncthreads();
    }

    #pragma unroll
    for (int i = 0; i < 4; i++) {
        float4 r = make_float4(acc[i][0], acc[i][1], acc[i][2], acc[i][3]);
        *(float4*)(out + (size_t)(mblk + m0 + i) * H + h0) = r;
    }
}

// ---------------------------------------------------------------------------
// Flash attention: BM=32 queries, BN=64 keys per tile, H=64, fp32.
// 256 threads = 16x16 grid, each thread 2m x 4n (and 2m x 4h for O).
// Row-stat reductions via shfl over the 16 lanes that share the same rows.
// Causal: tiles beyond diagonal skipped; diagonal tile masked.
// Scale (1/8) folded into Q at shared-load time.
// ---------------------------------------------------------------------------
__global__ __launch_bounds__(256) void attn_kernel(float* __restrict__ out)
{
    __shared__ float Qs[64 * 32];    // [h][m], stride 32
    __shared__ float KP[64 * 68];    // union: Ks [h][n] stride 68 ; Ps [n][m] stride 66
    __shared__ float Vs[64 * 68];    // [n][h], stride 68

    const int tid = threadIdx.x;
    const int tm  = tid >> 4;        // 0..15 -> 2 rows each
    const int tn  = tid & 15;        // 0..15 -> 4 cols each
    const int m0  = tm * 2;
    const int c0  = tn * 4;          // n-offset in S, h-offset in O
    const int b   = blockIdx.y;
    const int qt  = blockIdx.x;
    const int q0  = qt * 32;

    const float* qg = g_q + (size_t)b * T * H;
    const float* kg = g_k + (size_t)b * T * H;
    const float* vg = g_v + (size_t)b * T * H;

    // Load Q tile (scaled by 1/sqrt(H) = 0.125): 32x64 = 512 float4
    #pragma unroll
    for (int i = 0; i < 2; i++) {
        int idx = i * 256 + tid;
        int m  = idx >> 4;           // 0..31
        int hq = idx & 15;           // 0..15
        float4 a = *(const float4*)(qg + (size_t)(q0 + m) * H + hq * 4);
        Qs[(hq * 4 + 0) * 32 + m] = a.x * 0.125f;
        Qs[(hq * 4 + 1) * 32 + m] = a.y * 0.125f;
        Qs[(hq * 4 + 2) * 32 + m] = a.z * 0.125f;
        Qs[(hq * 4 + 3) * 32 + m] = a.w * 0.125f;
    }

    float o[2][4]  = {};
    float run_m[2] = {-1e30f, -1e30f};
    float run_l[2] = {0.f, 0.f};

    const int kt_last = (q0 + 31) >> 6;
    for (int kt = 0; kt <= kt_last; kt++) {
        const int k0 = kt * 64;

        __syncthreads();   // previous PV reads done (and Qs visible on first iter)

        // Load K -> KP [h][n], V -> Vs [n][h] : 64x64 = 1024 float4, 4/thread
        #pragma unroll
        for (int i = 0; i < 4; i++) {
            int idx = i * 256 + tid;
            int n  = idx >> 4;       // 0..63
            int hq = idx & 15;       // 0..15
            float4 ka = *(const float4*)(kg + (size_t)(k0 + n) * H + hq * 4);
            KP[(hq * 4 + 0) * 68 + n] = ka.x;
            KP[(hq * 4 + 1) * 68 + n] = ka.y;
            KP[(hq * 4 + 2) * 68 + n] = ka.z;
            KP[(hq * 4 + 3) * 68 + n] = ka.w;
            float4 va = *(const float4*)(vg + (size_t)(k0 + n) * H + hq * 4);
            *(float4*)&Vs[n * 68 + hq * 4] = va;
        }
        __syncthreads();

        // S = Q K^T  (2x4 per thread)
        float s[2][4] = {};
        #pragma unroll
        for (int h = 0; h < 64; h++) {
            float2 a  = *(const float2*)&Qs[h * 32 + m0];
            float4 bk = *(const float4*)&KP[h * 68 + c0];
            s[0][0] += a.x * bk.x; s[0][1] += a.x * bk.y; s[0][2] += a.x * bk.z; s[0][3] += a.x * bk.w;
            s[1][0] += a.y * bk.x; s[1][1] += a.y * bk.y; s[1][2] += a.y * bk.z; s[1][3] += a.y * bk.w;
        }

        // Causal mask on the last (diagonal) tile
        if (kt == kt_last) {
            #pragma unroll
            for (int i = 0; i < 2; i++)
                #pragma unroll
                for (int j = 0; j < 4; j++)
                    if (k0 + c0 + j > q0 + m0 + i) s[i][j] = -1e30f;
        }

        // Online softmax update
        #pragma unroll
        for (int i = 0; i < 2; i++) {
            float pm = fmaxf(fmaxf(s[i][0], s[i][1]), fmaxf(s[i][2], s[i][3]));
            pm = fmaxf(pm, __shfl_xor_sync(0xffffffffu, pm, 1));
            pm = fmaxf(pm, __shfl_xor_sync(0xffffffffu, pm, 2));
            pm = fmaxf(pm, __shfl_xor_sync(0xffffffffu, pm, 4));
            pm = fmaxf(pm, __shfl_xor_sync(0xffffffffu, pm, 8));
            float nm    = fmaxf(run_m[i], pm);
            float alpha = __expf(run_m[i] - nm);
            float rs = 0.f;
            #pragma unroll
            for (int j = 0; j < 4; j++) {
                s[i][j] = __expf(s[i][j] - nm);
                rs += s[i][j];
            }
            rs += __shfl_xor_sync(0xffffffffu, rs, 1);
            rs += __shfl_xor_sync(0xffffffffu, rs, 2);
            rs += __shfl_xor_sync(0xffffffffu, rs, 4);
            rs += __shfl_xor_sync(0xffffffffu, rs, 8);
            run_l[i] = run_l[i] * alpha + rs;
            run_m[i] = nm;
            #pragma unroll
            for (int j = 0; j < 4; j++) o[i][j] *= alpha;
        }

        __syncthreads();   // everyone done reading KP as Ks

        // Store P -> KP as Ps [n][m], stride 66
        #pragma unroll
        for (int i = 0; i < 2; i++)
            #pragma unroll
            for (int j = 0; j < 4; j++)
                KP[(c0 + j) * 66 + m0 + i] = s[i][j];
        __syncthreads();

        // O += P V
        #pragma unroll
        for (int n = 0; n < 64; n++) {
            float2 p  = *(const float2*)&KP[n * 66 + m0];
            float4 vv = *(const float4*)&Vs[n * 68 + c0];
            o[0][0] += p.x * vv.x; o[0][1] += p.x * vv.y; o[0][2] += p.x * vv.z; o[0][3] += p.x * vv.w;
            o[1][0] += p.y * vv.x; o[1][1] += p.y * vv.y; o[1][2] += p.y * vv.z; o[1][3] += p.y * vv.w;
        }
    }

    // Epilogue: normalize and write
    #pragma unroll
    for (int i = 0; i < 2; i++) {
        float inv = 1.0f / run_l[i];
        float4 r = make_float4(o[i][0] * inv, o[i][1] * inv, o[i][2] * inv, o[i][3] * inv);
        *(float4*)(out + ((size_t)b * T + q0 + m0 + i) * H + c0) = r;
    }
}

// ---------------------------------------------------------------------------
extern "C" void kernel_launch(void* const* d_in, const int* in_sizes, int n_in,
                              void* d_out, int out_size)
{
    const float* x  = (const float*)d_in[0];
    const float* Wq = (const float*)d_in[1];
    const float* Wk = (const float*)d_in[2];
    const float* Wv = (const float*)d_in[3];
    float* out = (float*)d_out;

    proj_kernel<<<dim3(M_TOTAL / 64, 3), 256>>>(x, Wq, Wk, Wv);
    attn_kernel<<<dim3(T / 32, BATCH), 256>>>(out);
}

// round 2
// speedup vs baseline: 1.1317x; 1.1317x over previous
#include <cuda_runtime.h>

#define BATCH 4
#define T 2048
#define C 1024
#define H 64
#define M_TOTAL (BATCH * T)   // 8192
#define NSPLIT 2

// Scratch (allocation-free rule: __device__ globals)
__device__ float g_q[BATCH * T * H];
__device__ float g_k[BATCH * T * H];
__device__ float g_v[BATCH * T * H];
__device__ float g_opart[NSPLIT][BATCH * T * H];   // unnormalized partial O
__device__ float g_m[NSPLIT][BATCH * T];           // running max per row
__device__ float g_l[NSPLIT][BATCH * T];           // running sum per row

// ---------------------------------------------------------------------------
// Projection: out[m][h] = sum_c x[m][c] * W[h][c]
// M=8192, N=H=64, K=1024.  BM=64, BN=64, BK=32.  256 threads, 4x4 microtile.
// ---------------------------------------------------------------------------
__global__ __launch_bounds__(256) void proj_kernel(
    const float* __restrict__ x,
    const float* __restrict__ Wq,
    const float* __restrict__ Wk,
    const float* __restrict__ Wv)
{
    const float* W;
    float* out;
    if (blockIdx.y == 0)      { W = Wq; out = g_q; }
    else if (blockIdx.y == 1) { W = Wk; out = g_k; }
    else                      { W = Wv; out = g_v; }

    __shared__ float As[32][68];
    __shared__ float Bs[32][68];

    const int tid = threadIdx.x;
    const int tm  = tid >> 4;
    const int tn  = tid & 15;
    const int m0  = tm * 4;
    const int h0  = tn * 4;
    const int mblk = blockIdx.x * 64;

    float acc[4][4] = {};

    for (int k0 = 0; k0 < C; k0 += 32) {
        #pragma unroll
        for (int i = 0; i < 2; i++) {
            int idx = i * 256 + tid;
            int row = idx >> 3;
            int kq  = idx & 7;
            float4 a = *(const float4*)(x + (size_t)(mblk + row) * C + k0 + kq * 4);
            As[kq * 4 + 0][row] = a.x;
            As[kq * 4 + 1][row] = a.y;
            As[kq * 4 + 2][row] = a.z;
            As[kq * 4 + 3][row] = a.w;
        }
        #pragma unroll
        for (int i = 0; i < 2; i++) {
            int idx = i * 256 + tid;
            int row = idx >> 3;
            int kq  = idx & 7;
            float4 b = *(const float4*)(W + (size_t)row * C + k0 + kq * 4);
            Bs[kq * 4 + 0][row] = b.x;
            Bs[kq * 4 + 1][row] = b.y;
            Bs[kq * 4 + 2][row] = b.z;
            Bs[kq * 4 + 3][row] = b.w;
        }
        __syncthreads();

        #pragma unroll
        for (int kk = 0; kk < 32; kk++) {
            float4 a = *(const float4*)&As[kk][m0];
            float4 b = *(const float4*)&Bs[kk][h0];
            acc[0][0] += a.x * b.x; acc[0][1] += a.x * b.y; acc[0][2] += a.x * b.z; acc[0][3] += a.x * b.w;
            acc[1][0] += a.y * b.x; acc[1][1] += a.y * b.y; acc[1][2] += a.y * b.z; acc[1][3] += a.y * b.w;
            acc[2][0] += a.z * b.x; acc[2][1] += a.z * b.y; acc[2][2] += a.z * b.z; acc[2][3] += a.z * b.w;
            acc[3][0] += a.w * b.x; acc[3][1] += a.w * b.y; acc[3][2] += a.w * b.z; acc[3][3] += a.w * b.w;
        }
        __syncthreads();
    }

    #pragma unroll
    for (int i = 0; i < 4; i++) {
        float4 r = make_float4(acc[i][0], acc[i][1], acc[i][2], acc[i][3]);
        *(float4*)(out + (size_t)(mblk + m0 + i) * H + h0) = r;
    }
}

// ---------------------------------------------------------------------------
// Flash attention partial: BM=32 queries, BN=64 keys/tile, H=64, fp32.
// KV range split across blockIdx.z in NSPLIT chunks of k-tiles.
// Emits UNNORMALIZED partial O + per-row (m, l) for the combine pass.
// blockIdx.x maps to q-tiles in DESCENDING work order (heavy-first).
// ---------------------------------------------------------------------------
__global__ __launch_bounds__(256) void attn_kernel()
{
    __shared__ float Qs[64 * 32];    // [h][m], stride 32
    __shared__ float KP[64 * 68];    // union: Ks [h][n] stride 68 ; Ps [n][m] stride 66
    __shared__ float Vs[64 * 68];    // [n][h], stride 68

    const int tid = threadIdx.x;
    const int tm  = tid >> 4;        // 0..15 -> 2 rows each
    const int tn  = tid & 15;        // 0..15 -> 4 cols each
    const int m0  = tm * 2;
    const int c0  = tn * 4;
    const int b   = blockIdx.y;
    const int qt  = (T / 32 - 1) - blockIdx.x;   // heavy-first
    const int sp  = blockIdx.z;
    const int q0  = qt * 32;

    // k-tile range for this split
    const int kt_last = (q0 + 31) >> 6;          // = qt>>1
    const int ntiles  = kt_last + 1;
    const int mid     = (ntiles + 1) >> 1;       // split0 gets ceil half
    const int kt_beg  = (sp == 0) ? 0   : mid;
    const int kt_end  = (sp == 0) ? mid : ntiles;

    const int r_base = b * T + q0;               // global row base for this tile

    if (kt_beg >= kt_end) {
        // empty split: write neutral partials
        #pragma unroll
        for (int i = 0; i < 2; i++) {
            *(float4*)&g_opart[sp][(size_t)(r_base + m0 + i) * H + c0] =
                make_float4(0.f, 0.f, 0.f, 0.f);
            if (tn == 0) {
                g_m[sp][r_base + m0 + i] = -1e30f;
                g_l[sp][r_base + m0 + i] = 0.f;
            }
        }
        return;
    }

    const float* qg = g_q + (size_t)b * T * H;
    const float* kg = g_k + (size_t)b * T * H;
    const float* vg = g_v + (size_t)b * T * H;

    // Load Q tile (scaled by 1/sqrt(H) = 0.125)
    #pragma unroll
    for (int i = 0; i < 2; i++) {
        int idx = i * 256 + tid;
        int m  = idx >> 4;
        int hq = idx & 15;
        float4 a = *(const float4*)(qg + (size_t)(q0 + m) * H + hq * 4);
        Qs[(hq * 4 + 0) * 32 + m] = a.x * 0.125f;
        Qs[(hq * 4 + 1) * 32 + m] = a.y * 0.125f;
        Qs[(hq * 4 + 2) * 32 + m] = a.z * 0.125f;
        Qs[(hq * 4 + 3) * 32 + m] = a.w * 0.125f;
    }

    float o[2][4]  = {};
    float run_m[2] = {-1e30f, -1e30f};
    float run_l[2] = {0.f, 0.f};

    for (int kt = kt_beg; kt < kt_end; kt++) {
        const int k0 = kt * 64;

        __syncthreads();

        // Load K -> KP [h][n], V -> Vs [n][h]
        #pragma unroll
        for (int i = 0; i < 4; i++) {
            int idx = i * 256 + tid;
            int n  = idx >> 4;
            int hq = idx & 15;
            float4 ka = *(const float4*)(kg + (size_t)(k0 + n) * H + hq * 4);
            KP[(hq * 4 + 0) * 68 + n] = ka.x;
            KP[(hq * 4 + 1) * 68 + n] = ka.y;
            KP[(hq * 4 + 2) * 68 + n] = ka.z;
            KP[(hq * 4 + 3) * 68 + n] = ka.w;
            float4 va = *(const float4*)(vg + (size_t)(k0 + n) * H + hq * 4);
            *(float4*)&Vs[n * 68 + hq * 4] = va;
        }
        __syncthreads();

        // S = Q K^T
        float s[2][4] = {};
        #pragma unroll
        for (int h = 0; h < 64; h++) {
            float2 a  = *(const float2*)&Qs[h * 32 + m0];
            float4 bk = *(const float4*)&KP[h * 68 + c0];
            s[0][0] += a.x * bk.x; s[0][1] += a.x * bk.y; s[0][2] += a.x * bk.z; s[0][3] += a.x * bk.w;
            s[1][0] += a.y * bk.x; s[1][1] += a.y * bk.y; s[1][2] += a.y * bk.z; s[1][3] += a.y * bk.w;
        }

        // Causal mask on the diagonal tile
        if (kt == kt_last) {
            #pragma unroll
            for (int i = 0; i < 2; i++)
                #pragma unroll
                for (int j = 0; j < 4; j++)
                    if (k0 + c0 + j > q0 + m0 + i) s[i][j] = -1e30f;
        }

        // Online softmax update
        #pragma unroll
        for (int i = 0; i < 2; i++) {
            float pm = fmaxf(fmaxf(s[i][0], s[i][1]), fmaxf(s[i][2], s[i][3]));
            pm = fmaxf(pm, __shfl_xor_sync(0xffffffffu, pm, 1));
            pm = fmaxf(pm, __shfl_xor_sync(0xffffffffu, pm, 2));
            pm = fmaxf(pm, __shfl_xor_sync(0xffffffffu, pm, 4));
            pm = fmaxf(pm, __shfl_xor_sync(0xffffffffu, pm, 8));
            float nm    = fmaxf(run_m[i], pm);
            float alpha = __expf(run_m[i] - nm);
            float rs = 0.f;
            #pragma unroll
            for (int j = 0; j < 4; j++) {
                s[i][j] = __expf(s[i][j] - nm);
                rs += s[i][j];
            }
            rs += __shfl_xor_sync(0xffffffffu, rs, 1);
            rs += __shfl_xor_sync(0xffffffffu, rs, 2);
            rs += __shfl_xor_sync(0xffffffffu, rs, 4);
            rs += __shfl_xor_sync(0xffffffffu, rs, 8);
            run_l[i] = run_l[i] * alpha + rs;
            run_m[i] = nm;
            #pragma unroll
            for (int j = 0; j < 4; j++) o[i][j] *= alpha;
        }

        __syncthreads();

        // Store P -> KP as Ps [n][m], stride 66
        #pragma unroll
        for (int i = 0; i < 2; i++)
            #pragma unroll
            for (int j = 0; j < 4; j++)
                KP[(c0 + j) * 66 + m0 + i] = s[i][j];
        __syncthreads();

        // O += P V
        #pragma unroll
        for (int n = 0; n < 64; n++) {
            float2 p  = *(const float2*)&KP[n * 66 + m0];
            float4 vv = *(const float4*)&Vs[n * 68 + c0];
            o[0][0] += p.x * vv.x; o[0][1] += p.x * vv.y; o[0][2] += p.x * vv.z; o[0][3] += p.x * vv.w;
            o[1][0] += p.y * vv.x; o[1][1] += p.y * vv.y; o[1][2] += p.y * vv.z; o[1][3] += p.y * vv.w;
        }
    }

    // Write UNNORMALIZED partial O + stats
    #pragma unroll
    for (int i = 0; i < 2; i++) {
        *(float4*)&g_opart[sp][(size_t)(r_base + m0 + i) * H + c0] =
            make_float4(o[i][0], o[i][1], o[i][2], o[i][3]);
        if (tn == 0) {
            g_m[sp][r_base + m0 + i] = run_m[i];
            g_l[sp][r_base + m0 + i] = run_l[i];
        }
    }
}

// ---------------------------------------------------------------------------
// Combine the NSPLIT partials:
//   out = (w1*O1 + w2*O2) / (w1*l1 + w2*l2),  wi = exp(mi - max(m1,m2))
// One thread per 4 output floats: 8192 rows * 16 units = 131072 threads.
// ---------------------------------------------------------------------------
__global__ __launch_bounds__(256) void combine_kernel(float* __restrict__ out)
{
    int idx = blockIdx.x * 256 + threadIdx.x;
    int row = idx >> 4;
    int c4  = (idx & 15) * 4;

    float m1 = g_m[0][row], m2 = g_m[1][row];
    float l1 = g_l[0][row], l2 = g_l[1][row];
    float M  = fmaxf(m1, m2);
    float w1 = __expf(m1 - M);
    float w2 = __expf(m2 - M);
    float inv = 1.0f / (w1 * l1 + w2 * l2);

    float4 o1 = *(const float4*)&g_opart[0][(size_t)row * H + c4];
    float4 o2 = *(const float4*)&g_opart[1][(size_t)row * H + c4];
    float4 r;
    r.x = (w1 * o1.x + w2 * o2.x) * inv;
    r.y = (w1 * o1.y + w2 * o2.y) * inv;
    r.z = (w1 * o1.z + w2 * o2.z) * inv;
    r.w = (w1 * o1.w + w2 * o2.w) * inv;
    *(float4*)&out[(size_t)row * H + c4] = r;
}

// ---------------------------------------------------------------------------
extern "C" void kernel_launch(void* const* d_in, const int* in_sizes, int n_in,
                              void* d_out, int out_size)
{
    const float* x  = (const float*)d_in[0];
    const float* Wq = (const float*)d_in[1];
    const float* Wk = (const float*)d_in[2];
    const float* Wv = (const float*)d_in[3];
    float* out = (float*)d_out;

    proj_kernel<<<dim3(M_TOTAL / 64, 3), 256>>>(x, Wq, Wk, Wv);
    attn_kernel<<<dim3(T / 32, BATCH, NSPLIT), 256>>>();
    combine_kernel<<<(M_TOTAL * (H / 4)) / 256, 256>>>(out);
}